// round 4
// baseline (speedup 1.0000x reference)
#include <cuda_runtime.h>

typedef unsigned long long u64;

// packed f32x2 helpers (sm_100+ PTX; doubles FFMA throughput)
__device__ __forceinline__ u64 pk2(float lo, float hi) {
    u64 r; asm("mov.b64 %0,{%1,%2};" : "=l"(r) : "f"(lo), "f"(hi)); return r;
}
__device__ __forceinline__ u64 fma2(u64 a, u64 b, u64 c) {
    u64 d; asm("fma.rn.f32x2 %0,%1,%2,%3;" : "=l"(d) : "l"(a), "l"(b), "l"(c)); return d;
}
__device__ __forceinline__ float sum2(u64 a) {
    float lo, hi; asm("mov.b64 {%0,%1},%2;" : "=f"(lo), "=f"(hi) : "l"(a)); return lo + hi;
}
__device__ __forceinline__ unsigned smem_u32(const void* p) {
    unsigned a;
    asm("{ .reg .u64 t; cvta.to.shared.u64 t, %1; cvt.u32.u64 %0, t; }" : "=r"(a) : "l"(p));
    return a;
}
__device__ __forceinline__ void cp_async16(unsigned s, const void* g) {
    asm volatile("cp.async.cg.shared.global [%0], [%1], 16;" :: "r"(s), "l"(g));
}

// Scratch (allocation-free rule: __device__ globals)
__device__ float g_n1[2048 * 8];     // n1[row][k]
__device__ float g_n2T[6 * 2048];    // n2 transposed [k][row] -> coalesced reads in k_adj

// ---------------------------------------------------------------------------
// Merged: t = mean_h(wa) @ x ; gcn = relu(t@W^T+b) ; out = gcn@Wxx^T+b ;
//         n1 = gcn@Wn1^T ; n2 = gcn@Wn2^T
// grid = B*(L/4) = 512 blocks, 256 threads (two 128-thread halves split j)
// 4 output rows (i) per block -> 3.46 blocks/SM, short dependence chains.
// ---------------------------------------------------------------------------
__global__ void __launch_bounds__(256) k_gcn(const float* __restrict__ x,
                                             const float* __restrict__ wa,
                                             const float* __restrict__ Ww,
                                             const float* __restrict__ Wb,
                                             const float* __restrict__ Wx_w,
                                             const float* __restrict__ Wxx,
                                             const float* __restrict__ Wxxb,
                                             float* __restrict__ out) {
    __shared__ __align__(16) float pool[8192];    // x tiles -> t partials -> w tiles
    __shared__ __align__(16) float a_s[2][128];
    __shared__ __align__(16) float t_s[512];
    __shared__ __align__(16) float g_s[512];

    int b    = blockIdx.x >> 6;
    int i0   = (blockIdx.x & 63) << 2;
    int tid  = threadIdx.x;
    int lane = tid & 127;
    int half = tid >> 7;
    int r0   = blockIdx.x * 4;
    const float inv6 = 1.0f / 6.0f;

    // ---------- Phase A: t = mean_h(wa) @ x, halves split the j-range ----------
    float* x_s = pool + half * 4096;
    u64 acc2[4];
    #pragma unroll
    for (int ii = 0; ii < 4; ii++) acc2[ii] = 0ull;

    for (int jt = 0; jt < 4; jt++) {
        int j0 = half * 128 + jt * 32;
        const float4* xs = (const float4*)(x + ((long)b * 256 + j0) * 128);
        float4*       xd = (float4*)x_s;
        #pragma unroll
        for (int idx = lane; idx < 1024; idx += 128) xd[idx] = xs[idx];
        {   // adj_avg tile: 128 entries = 4 i x 32 j, one per lane
            int ii = lane >> 5, jj = lane & 31;
            float s = 0.0f;
            #pragma unroll
            for (int h = 0; h < 6; h++)
                s += wa[(((long)(b * 6 + h) * 256) + i0 + ii) * 256 + j0 + jj];
            a_s[half][lane] = s * inv6;
        }
        __syncthreads();
        #pragma unroll
        for (int g = 0; g < 32; g += 4) {
            float xv0 = x_s[(g + 0) * 128 + lane];
            float xv1 = x_s[(g + 1) * 128 + lane];
            float xv2 = x_s[(g + 2) * 128 + lane];
            float xv3 = x_s[(g + 3) * 128 + lane];
            u64 xp0 = pk2(xv0, xv1), xp1 = pk2(xv2, xv3);
            #pragma unroll
            for (int ii = 0; ii < 4; ii++) {
                const u64* ap = (const u64*)&a_s[half][ii * 32 + g];   // broadcast LDS.64
                acc2[ii] = fma2(ap[0], xp0, acc2[ii]);
                acc2[ii] = fma2(ap[1], xp1, acc2[ii]);
            }
        }
        __syncthreads();
    }
    // reduce the two halves via pool
    #pragma unroll
    for (int ii = 0; ii < 4; ii++) pool[half * 512 + ii * 128 + lane] = sum2(acc2[ii]);
    __syncthreads();
    #pragma unroll
    for (int idx = tid; idx < 512; idx += 256) t_s[idx] = pool[idx] + pool[512 + idx];
    __syncthreads();

    // ---------- Phase B: gcn = relu(t @ Ww^T + b), halves split rows ----------
    float* w_s = pool;   // 32 x 129 tile, conflict-free transpose staging
    u64 b2[2];
    b2[0] = b2[1] = 0ull;
    for (int kt = 0; kt < 4; kt++) {
        int k0 = kt * 32;
        #pragma unroll
        for (int idx = tid; idx < 4096; idx += 256) {
            int d = idx >> 5, c = idx & 31;
            w_s[c * 129 + d] = Ww[d * 128 + k0 + c];   // coalesced read, cf write
        }
        __syncthreads();
        #pragma unroll
        for (int kk = 0; kk < 32; kk += 2) {
            u64 wp = pk2(w_s[kk * 129 + lane], w_s[(kk + 1) * 129 + lane]);
            #pragma unroll
            for (int r = 0; r < 2; r++) {
                u64 t2 = *(const u64*)&t_s[(half * 2 + r) * 128 + k0 + kk];  // broadcast
                b2[r] = fma2(t2, wp, b2[r]);
            }
        }
        __syncthreads();
    }
    float bb = Wb[lane];
    #pragma unroll
    for (int r = 0; r < 2; r++)
        g_s[(half * 2 + r) * 128 + lane] = fmaxf(sum2(b2[r]) + bb, 0.0f);
    __syncthreads();

    // ---------- Phase C: out = gcn @ Wxx^T + b ----------
    u64 o2[2];
    o2[0] = o2[1] = 0ull;
    for (int kt = 0; kt < 4; kt++) {
        int k0 = kt * 32;
        #pragma unroll
        for (int idx = tid; idx < 4096; idx += 256) {
            int d = idx >> 5, c = idx & 31;
            w_s[c * 129 + d] = Wxx[d * 128 + k0 + c];
        }
        __syncthreads();
        #pragma unroll
        for (int kk = 0; kk < 32; kk += 2) {
            u64 wp = pk2(w_s[kk * 129 + lane], w_s[(kk + 1) * 129 + lane]);
            #pragma unroll
            for (int r = 0; r < 2; r++) {
                u64 g2 = *(const u64*)&g_s[(half * 2 + r) * 128 + k0 + kk];
                o2[r] = fma2(g2, wp, o2[r]);
            }
        }
        __syncthreads();
    }
    float ob = Wxxb[lane];
    #pragma unroll
    for (int r = 0; r < 2; r++)
        out[(long)(r0 + half * 2 + r) * 128 + lane] = sum2(o2[r]) + ob;

    // ---------- Phase D: n1/n2 — 48 dots of length 128 ----------
    if (tid < 48) {
        int sel = tid >= 24;                // 0 -> n1, 1 -> n2
        int q   = tid - sel * 24;
        int r   = q / 6, k = q % 6;
        const float* g = &g_s[r * 128];
        const float* w = Wx_w + k * 294 + 6 + sel * 128;
        u64 s = 0ull;
        #pragma unroll 8
        for (int d = 0; d < 128; d += 2)
            s = fma2(*(const u64*)&g[d], pk2(__ldg(&w[d]), __ldg(&w[d + 1])), s);
        float v = sum2(s);
        if (sel == 0) g_n1[(r0 + r) * 8 + k]   = v;
        else          g_n2T[k * 2048 + r0 + r] = v;
    }
}

// ---------------------------------------------------------------------------
// new_adj[b,k,i,j] = sum_h wa[b,h,i,j]*Wa[k,h] + n1[b,i,k] + n2[b,j,k]
//                  + sum_e e[b,i,j,e]*We[k,e] + Wx_b[k]
// grid = B*L = 2048 blocks (one per (b,i)), 256 threads (thread = j)
// e tile staged via cp.async.cg (no regs, L1 bypass) -> low regs, 6 blocks/SM
// ---------------------------------------------------------------------------
__global__ void __launch_bounds__(256, 6) k_adj(const float* __restrict__ wa,
                                                const float* __restrict__ e,
                                                const float* __restrict__ Wx_w,
                                                const float* __restrict__ Wx_b,
                                                float* __restrict__ adj_out) {
    __shared__ __align__(16) float e_s[256 * 36];  // [j][ee] pad 36: .128 reads, cf
    __shared__ __align__(16) float Wa_s[40];       // [k*6+h]
    __shared__ __align__(16) float We_s[200];      // [k*32+ee]
    __shared__ __align__(16) float n1b_s[16];      // n1 @0..5, bias @8..13
    int b   = blockIdx.x >> 8;
    int i   = blockIdx.x & 255;
    int tid = threadIdx.x;

    // async-stage e[b,i,:,:] (32KB contiguous): 8 x cp.async.cg per thread
    const float4* e4 = (const float4*)(e + (((long)b * 256 + i) * 256) * 32);
    #pragma unroll
    for (int it = 0; it < 8; it++) {
        int idx = tid + it * 256;
        unsigned dst = smem_u32(&e_s[(idx >> 3) * 36 + (idx & 7) * 4]);
        cp_async16(dst, &e4[idx]);
    }
    asm volatile("cp.async.commit_group;" ::: "memory");

    // overlap: scalar loads while the bulk copy is in flight
    float wv[6];
    #pragma unroll
    for (int h = 0; h < 6; h++)
        wv[h] = wa[(((long)(b * 6 + h) * 256) + i) * 256 + tid];
    float n2v[6];
    #pragma unroll
    for (int k = 0; k < 6; k++) n2v[k] = g_n2T[k * 2048 + b * 256 + tid];
    if (tid < 36) Wa_s[tid] = Wx_w[(tid / 6) * 294 + tid % 6];
    if (tid >= 64 && tid < 256) {
        int t = tid - 64;
        We_s[t] = Wx_w[(t >> 5) * 294 + 262 + (t & 31)];
    }
    if (tid >= 40 && tid < 46) n1b_s[tid - 40]     = g_n1[((long)b * 256 + i) * 8 + (tid - 40)];
    if (tid >= 48 && tid < 54) n1b_s[8 + tid - 48] = Wx_b[tid - 48];

    asm volatile("cp.async.wait_group 0;" ::: "memory");
    __syncthreads();

    u64 acc2[6];
    #pragma unroll
    for (int k = 0; k < 6; k++) acc2[k] = 0ull;

    // adj term: 3 packed h-pairs x 6 k
    u64 wp0 = pk2(wv[0], wv[1]), wp1 = pk2(wv[2], wv[3]), wp2 = pk2(wv[4], wv[5]);
    #pragma unroll
    for (int k = 0; k < 6; k++) {
        acc2[k] = fma2(*(const u64*)&Wa_s[k * 6 + 0], wp0, acc2[k]);
        acc2[k] = fma2(*(const u64*)&Wa_s[k * 6 + 2], wp1, acc2[k]);
        acc2[k] = fma2(*(const u64*)&Wa_s[k * 6 + 4], wp2, acc2[k]);
    }

    // e term: 8 x LDS.128 (conflict-free), 16 packed ee-pairs x 6 k
    const float4* ep = (const float4*)&e_s[tid * 36];
    #pragma unroll
    for (int q = 0; q < 8; q++) {
        float4 w = ep[q];
        u64 ev0 = pk2(w.x, w.y);
        u64 ev1 = pk2(w.z, w.w);
        #pragma unroll
        for (int k = 0; k < 6; k++) {
            acc2[k] = fma2(ev0, *(const u64*)&We_s[k * 32 + q * 4 + 0], acc2[k]);
            acc2[k] = fma2(ev1, *(const u64*)&We_s[k * 32 + q * 4 + 2], acc2[k]);
        }
    }

    long ob = ((long)(b * 6) * 65536) + (long)i * 256 + tid;
    #pragma unroll
    for (int k = 0; k < 6; k++)
        adj_out[ob + (long)k * 65536] = sum2(acc2[k]) + n1b_s[k] + n1b_s[8 + k] + n2v[k];
}

// ---------------------------------------------------------------------------
extern "C" void kernel_launch(void* const* d_in, const int* in_sizes, int n_in,
                              void* d_out, int out_size) {
    const float* x     = (const float*)d_in[0];
    const float* wa    = (const float*)d_in[1];
    const float* e     = (const float*)d_in[2];
    const float* W_w   = (const float*)d_in[3];
    const float* W_b   = (const float*)d_in[4];
    const float* Wx_w  = (const float*)d_in[5];
    const float* Wx_b  = (const float*)d_in[6];
    const float* Wxx_w = (const float*)d_in[7];
    const float* Wxx_b = (const float*)d_in[8];

    float* out     = (float*)d_out;            // (B,L,D) = 262144 floats
    float* adj_out = out + 8 * 256 * 128;      // (B,H,L,L) = 3145728 floats

    k_gcn<<<512, 256>>>(x, wa, W_w, W_b, Wx_w, Wxx_w, Wxx_b, out);
    k_adj<<<2048, 256>>>(wa, e, Wx_w, Wx_b, adj_out);
}

// round 5
// speedup vs baseline: 1.1425x; 1.1425x over previous
#include <cuda_runtime.h>

typedef unsigned long long u64;

// packed f32x2 helpers (sm_100+ PTX; doubles FFMA throughput)
__device__ __forceinline__ u64 pk2(float lo, float hi) {
    u64 r; asm("mov.b64 %0,{%1,%2};" : "=l"(r) : "f"(lo), "f"(hi)); return r;
}
__device__ __forceinline__ u64 fma2(u64 a, u64 b, u64 c) {
    u64 d; asm("fma.rn.f32x2 %0,%1,%2,%3;" : "=l"(d) : "l"(a), "l"(b), "l"(c)); return d;
}
__device__ __forceinline__ float sum2(u64 a) {
    float lo, hi; asm("mov.b64 {%0,%1},%2;" : "=f"(lo), "=f"(hi) : "l"(a)); return lo + hi;
}
__device__ __forceinline__ unsigned smem_u32(const void* p) {
    unsigned a;
    asm("{ .reg .u64 t; cvta.to.shared.u64 t, %1; cvt.u32.u64 %0, t; }" : "=r"(a) : "l"(p));
    return a;
}
__device__ __forceinline__ void cp_async16(unsigned s, const void* g) {
    asm volatile("cp.async.cg.shared.global [%0], [%1], 16;" :: "r"(s), "l"(g));
}

// Scratch (allocation-free rule: __device__ globals)
__device__ float g_n1[2048 * 8];     // n1[row][k]
__device__ float g_n2T[6 * 2048];    // n2 transposed [k][row]

// ---------------------------------------------------------------------------
// Merged: t = mean_h(wa) @ x ; gcn = relu(t@W^T+b) ; out = gcn@Wxx^T+b ;
//         n1 = gcn@Wn1^T ; n2 = gcn@Wn2^T
// grid = B*(L/8) = 256 blocks, 512 threads.
// Work split: group g = tid>>7 -> (row-half rh = g&1) x (j-half jh = g>>1).
// ---------------------------------------------------------------------------
__global__ void __launch_bounds__(512) k_gcn(const float* __restrict__ x,
                                             const float* __restrict__ wa,
                                             const float* __restrict__ Ww,
                                             const float* __restrict__ Wb,
                                             const float* __restrict__ Wx_w,
                                             const float* __restrict__ Wxx,
                                             const float* __restrict__ Wxxb,
                                             float* __restrict__ out) {
    __shared__ __align__(16) float pool[8192];   // x tiles -> t partials -> w tiles
    __shared__ __align__(16) float a_s[4][128];
    __shared__ __align__(16) float t_s[1024];
    __shared__ __align__(16) float g_s[1024];

    int b    = blockIdx.x >> 5;
    int i0   = (blockIdx.x & 31) << 3;
    int tid  = threadIdx.x;
    int g    = tid >> 7;
    int lane = tid & 127;
    int rh   = g & 1;          // row-half: rows rh*4 .. rh*4+3
    int jh   = g >> 1;         // j-half:   j in [jh*128, jh*128+128)
    int jtid = tid & 255;      // thread id within j-half (256 threads)
    int r0   = blockIdx.x * 8;
    const float inv6 = 1.0f / 6.0f;

    // ---------- Phase A: t = mean_h(wa) @ x ----------
    float* x_s = pool + jh * 4096;
    u64 acc[4];
    #pragma unroll
    for (int ii = 0; ii < 4; ii++) acc[ii] = 0ull;

    for (int jt = 0; jt < 4; jt++) {
        int j0 = jh * 128 + jt * 32;
        const float4* xs = (const float4*)(x + ((long)b * 256 + j0) * 128);
        float4*       xd = (float4*)x_s;
        #pragma unroll
        for (int idx = jtid; idx < 1024; idx += 256) xd[idx] = xs[idx];
        {   // adj_avg tile: 4 rows x 32 j, one entry per lane
            int ii = lane >> 5, jj = lane & 31;
            float s = 0.0f;
            #pragma unroll
            for (int h = 0; h < 6; h++)
                s += wa[(((long)(b * 6 + h) * 256) + i0 + rh * 4 + ii) * 256 + j0 + jj];
            a_s[g][lane] = s * inv6;
        }
        __syncthreads();
        #pragma unroll
        for (int gg = 0; gg < 32; gg += 4) {
            float xv0 = x_s[(gg + 0) * 128 + lane];
            float xv1 = x_s[(gg + 1) * 128 + lane];
            float xv2 = x_s[(gg + 2) * 128 + lane];
            float xv3 = x_s[(gg + 3) * 128 + lane];
            u64 xp0 = pk2(xv0, xv1), xp1 = pk2(xv2, xv3);
            #pragma unroll
            for (int ii = 0; ii < 4; ii++) {
                const u64* ap = (const u64*)&a_s[g][ii * 32 + gg];   // broadcast LDS.64
                acc[ii] = fma2(ap[0], xp0, acc[ii]);
                acc[ii] = fma2(ap[1], xp1, acc[ii]);
            }
        }
        __syncthreads();
    }
    // partials -> pool, then reduce the two j-halves
    #pragma unroll
    for (int ii = 0; ii < 4; ii++) pool[g * 512 + ii * 128 + lane] = sum2(acc[ii]);
    __syncthreads();
    #pragma unroll
    for (int idx = tid; idx < 1024; idx += 512) {
        int r = idx >> 7, c = idx & 127;
        int rhh = r >> 2, rr = r & 3;
        t_s[idx] = pool[rhh * 512 + rr * 128 + c] + pool[(2 + rhh) * 512 + rr * 128 + c];
    }
    __syncthreads();

    // ---------- Phase B: gcn = relu(t @ Ww^T + b), 2 rows per group ----------
    float* w_s = pool;   // 32 x 129 tile, conflict-free transpose staging
    u64 b2[2];
    b2[0] = b2[1] = 0ull;
    for (int kt = 0; kt < 4; kt++) {
        int k0 = kt * 32;
        #pragma unroll
        for (int idx = tid; idx < 4096; idx += 512) {
            int d = idx >> 5, c = idx & 31;
            w_s[c * 129 + d] = Ww[d * 128 + k0 + c];   // coalesced read, cf write
        }
        __syncthreads();
        #pragma unroll
        for (int kk = 0; kk < 32; kk += 2) {
            u64 wp = pk2(w_s[kk * 129 + lane], w_s[(kk + 1) * 129 + lane]);
            #pragma unroll
            for (int r = 0; r < 2; r++) {
                u64 t2 = *(const u64*)&t_s[(g * 2 + r) * 128 + k0 + kk];  // broadcast
                b2[r] = fma2(t2, wp, b2[r]);
            }
        }
        __syncthreads();
    }
    float bb = Wb[lane];
    #pragma unroll
    for (int r = 0; r < 2; r++)
        g_s[(g * 2 + r) * 128 + lane] = fmaxf(sum2(b2[r]) + bb, 0.0f);
    __syncthreads();

    // ---------- Phase C: out = gcn @ Wxx^T + b ----------
    u64 o2[2];
    o2[0] = o2[1] = 0ull;
    for (int kt = 0; kt < 4; kt++) {
        int k0 = kt * 32;
        #pragma unroll
        for (int idx = tid; idx < 4096; idx += 512) {
            int d = idx >> 5, c = idx & 31;
            w_s[c * 129 + d] = Wxx[d * 128 + k0 + c];
        }
        __syncthreads();
        #pragma unroll
        for (int kk = 0; kk < 32; kk += 2) {
            u64 wp = pk2(w_s[kk * 129 + lane], w_s[(kk + 1) * 129 + lane]);
            #pragma unroll
            for (int r = 0; r < 2; r++) {
                u64 g2 = *(const u64*)&g_s[(g * 2 + r) * 128 + k0 + kk];
                o2[r] = fma2(g2, wp, o2[r]);
            }
        }
        __syncthreads();
    }
    float ob = Wxxb[lane];
    #pragma unroll
    for (int r = 0; r < 2; r++)
        out[(long)(r0 + g * 2 + r) * 128 + lane] = sum2(o2[r]) + ob;

    // ---------- Phase D: n1/n2 — 96 dots of length 128 ----------
    if (tid < 96) {
        int sel = tid >= 48;                // 0 -> n1, 1 -> n2
        int q   = tid - sel * 48;
        int r   = q / 6, k = q % 6;
        const float* gp = &g_s[r * 128];
        const float* w  = Wx_w + k * 294 + 6 + sel * 128;
        u64 s = 0ull;
        #pragma unroll 8
        for (int d = 0; d < 128; d += 2)
            s = fma2(*(const u64*)&gp[d], pk2(__ldg(&w[d]), __ldg(&w[d + 1])), s);
        float v = sum2(s);
        if (sel == 0) g_n1[(r0 + r) * 8 + k]   = v;
        else          g_n2T[k * 2048 + r0 + r] = v;
    }
}

// ---------------------------------------------------------------------------
// new_adj[b,k,i,j] = sum_h wa[b,h,i,j]*Wa[k,h] + n1[b,i,k] + n2[b,j,k]
//                  + sum_e e[b,i,j,e]*We[k,e] + Wx_b[k]
// grid = B*L = 2048 blocks (one per (b,i)), 256 threads (thread = j)
// PDL: heavy phase (e + adj terms) runs BEFORE the grid dependency sync,
// overlapping with k_gcn; n1/n2 are read only after the sync.
// ---------------------------------------------------------------------------
__global__ void __launch_bounds__(256) k_adj(const float* __restrict__ wa,
                                             const float* __restrict__ e,
                                             const float* __restrict__ Wx_w,
                                             const float* __restrict__ Wx_b,
                                             float* __restrict__ adj_out) {
    __shared__ __align__(16) float e_s[256 * 36];  // [j][ee] pad 36: .128 reads, cf
    __shared__ __align__(16) float Wa_s[40];       // [k*6+h]
    __shared__ __align__(16) float We_s[200];      // [k*32+ee]
    __shared__ __align__(16) float n1b_s[16];      // n1 @0..5, bias @8..13
    int b   = blockIdx.x >> 8;
    int i   = blockIdx.x & 255;
    int tid = threadIdx.x;

    // async-stage e[b,i,:,:] (32KB contiguous): 8 x cp.async.cg per thread
    const float4* e4 = (const float4*)(e + (((long)b * 256 + i) * 256) * 32);
    #pragma unroll
    for (int it = 0; it < 8; it++) {
        int idx = tid + it * 256;
        unsigned dst = smem_u32(&e_s[(idx >> 3) * 36 + (idx & 7) * 4]);
        cp_async16(dst, &e4[idx]);
    }
    asm volatile("cp.async.commit_group;" ::: "memory");

    // overlap: scalar input loads while the bulk copy is in flight
    float wv[6];
    #pragma unroll
    for (int h = 0; h < 6; h++)
        wv[h] = wa[(((long)(b * 6 + h) * 256) + i) * 256 + tid];
    if (tid < 36) Wa_s[tid] = Wx_w[(tid / 6) * 294 + tid % 6];
    if (tid >= 64 && tid < 256) {
        int t = tid - 64;
        We_s[t] = Wx_w[(t >> 5) * 294 + 262 + (t & 31)];
    }
    if (tid >= 48 && tid < 54) n1b_s[8 + tid - 48] = Wx_b[tid - 48];

    asm volatile("cp.async.wait_group 0;" ::: "memory");
    __syncthreads();

    u64 acc2[6];
    #pragma unroll
    for (int k = 0; k < 6; k++) acc2[k] = 0ull;

    // adj term: 3 packed h-pairs x 6 k
    u64 wp0 = pk2(wv[0], wv[1]), wp1 = pk2(wv[2], wv[3]), wp2 = pk2(wv[4], wv[5]);
    #pragma unroll
    for (int k = 0; k < 6; k++) {
        acc2[k] = fma2(*(const u64*)&Wa_s[k * 6 + 0], wp0, acc2[k]);
        acc2[k] = fma2(*(const u64*)&Wa_s[k * 6 + 2], wp1, acc2[k]);
        acc2[k] = fma2(*(const u64*)&Wa_s[k * 6 + 4], wp2, acc2[k]);
    }

    // e term: 8 x LDS.128 (conflict-free), 16 packed ee-pairs x 6 k
    const float4* ep = (const float4*)&e_s[tid * 36];
    #pragma unroll
    for (int q = 0; q < 8; q++) {
        float4 w = ep[q];
        u64 ev0 = pk2(w.x, w.y);
        u64 ev1 = pk2(w.z, w.w);
        #pragma unroll
        for (int k = 0; k < 6; k++) {
            acc2[k] = fma2(ev0, *(const u64*)&We_s[k * 32 + q * 4 + 0], acc2[k]);
            acc2[k] = fma2(ev1, *(const u64*)&We_s[k * 32 + q * 4 + 2], acc2[k]);
        }
    }

    // ---- only now do we need k_gcn's output ----
    cudaGridDependencySynchronize();

    if (tid < 6) n1b_s[tid] = g_n1[((long)b * 256 + i) * 8 + tid];
    float n2v[6];
    #pragma unroll
    for (int k = 0; k < 6; k++) n2v[k] = g_n2T[k * 2048 + b * 256 + tid];
    __syncthreads();

    long ob = ((long)(b * 6) * 65536) + (long)i * 256 + tid;
    #pragma unroll
    for (int k = 0; k < 6; k++)
        adj_out[ob + (long)k * 65536] = sum2(acc2[k]) + n1b_s[k] + n1b_s[8 + k] + n2v[k];
}

// ---------------------------------------------------------------------------
extern "C" void kernel_launch(void* const* d_in, const int* in_sizes, int n_in,
                              void* d_out, int out_size) {
    const float* x     = (const float*)d_in[0];
    const float* wa    = (const float*)d_in[1];
    const float* e     = (const float*)d_in[2];
    const float* W_w   = (const float*)d_in[3];
    const float* W_b   = (const float*)d_in[4];
    const float* Wx_w  = (const float*)d_in[5];
    const float* Wx_b  = (const float*)d_in[6];
    const float* Wxx_w = (const float*)d_in[7];
    const float* Wxx_b = (const float*)d_in[8];

    float* out     = (float*)d_out;            // (B,L,D) = 262144 floats
    float* adj_out = out + 8 * 256 * 128;      // (B,H,L,L) = 3145728 floats

    k_gcn<<<256, 512>>>(x, wa, W_w, W_b, Wx_w, Wxx_w, Wxx_b, out);

    // k_adj with programmatic dependent launch: overlaps its heavy phase
    // with k_gcn; cudaGridDependencySynchronize() guards the n1/n2 reads.
    cudaLaunchConfig_t cfg = {};
    cfg.gridDim  = dim3(2048);
    cfg.blockDim = dim3(256);
    cudaLaunchAttribute attr[1];
    attr[0].id = cudaLaunchAttributeProgrammaticStreamSerialization;
    attr[0].val.programmaticStreamSerializationAllowed = 1;
    cfg.attrs    = attr;
    cfg.numAttrs = 1;
    cudaLaunchKernelEx(&cfg, k_adj, wa, e, Wx_w, Wx_b, adj_out);
}

// round 6
// speedup vs baseline: 1.2060x; 1.0556x over previous
#include <cuda_runtime.h>

typedef unsigned long long u64;

// packed f32x2 helpers (sm_100+ PTX; doubles FFMA throughput)
__device__ __forceinline__ u64 pk2(float lo, float hi) {
    u64 r; asm("mov.b64 %0,{%1,%2};" : "=l"(r) : "f"(lo), "f"(hi)); return r;
}
__device__ __forceinline__ u64 fma2(u64 a, u64 b, u64 c) {
    u64 d; asm("fma.rn.f32x2 %0,%1,%2,%3;" : "=l"(d) : "l"(a), "l"(b), "l"(c)); return d;
}
__device__ __forceinline__ float sum2(u64 a) {
    float lo, hi; asm("mov.b64 {%0,%1},%2;" : "=f"(lo), "=f"(hi) : "l"(a)); return lo + hi;
}
__device__ __forceinline__ unsigned smem_u32(const void* p) {
    unsigned a;
    asm("{ .reg .u64 t; cvta.to.shared.u64 t, %1; cvt.u32.u64 %0, t; }" : "=r"(a) : "l"(p));
    return a;
}
__device__ __forceinline__ void cp_async16(unsigned s, const void* g) {
    asm volatile("cp.async.cg.shared.global [%0], [%1], 16;" :: "r"(s), "l"(g));
}

// Scratch (allocation-free rule: __device__ globals)
__device__ float g_n1[2048 * 8];     // n1[row][k]
__device__ float g_n2T[6 * 2048];    // n2 transposed [k][row]

// ---------------------------------------------------------------------------
// Merged: t = mean_h(wa) @ x ; gcn = relu(t@W^T+b) ; out = gcn@Wxx^T+b ;
//         n1 = gcn@Wn1^T ; n2 = gcn@Wn2^T
// grid = B*(L/8) = 256 blocks, 512 threads.
// Triggers programmatic launch completion IMMEDIATELY so the dependent
// k_adj grid co-schedules and overlaps its independent heavy phase.
// ---------------------------------------------------------------------------
__global__ void __launch_bounds__(512) k_gcn(const float* __restrict__ x,
                                             const float* __restrict__ wa,
                                             const float* __restrict__ Ww,
                                             const float* __restrict__ Wb,
                                             const float* __restrict__ Wx_w,
                                             const float* __restrict__ Wxx,
                                             const float* __restrict__ Wxxb,
                                             float* __restrict__ out) {
    cudaTriggerProgrammaticLaunchCompletion();   // let k_adj start now

    __shared__ __align__(16) float pool[8192];   // x tiles -> t partials -> w tiles
    __shared__ __align__(16) float a_s[4][128];
    __shared__ __align__(16) float t_s[1024];
    __shared__ __align__(16) float g_s[1024];

    int b    = blockIdx.x >> 5;
    int i0   = (blockIdx.x & 31) << 3;
    int tid  = threadIdx.x;
    int g    = tid >> 7;
    int lane = tid & 127;
    int rh   = g & 1;          // row-half: rows rh*4 .. rh*4+3
    int jh   = g >> 1;         // j-half:   j in [jh*128, jh*128+128)
    int jtid = tid & 255;      // thread id within j-half (256 threads)
    int r0   = blockIdx.x * 8;
    const float inv6 = 1.0f / 6.0f;

    // ---------- Phase A: t = mean_h(wa) @ x ----------
    float* x_s = pool + jh * 4096;
    u64 acc[4];
    #pragma unroll
    for (int ii = 0; ii < 4; ii++) acc[ii] = 0ull;

    for (int jt = 0; jt < 4; jt++) {
        int j0 = jh * 128 + jt * 32;
        const float4* xs = (const float4*)(x + ((long)b * 256 + j0) * 128);
        float4*       xd = (float4*)x_s;
        #pragma unroll
        for (int idx = jtid; idx < 1024; idx += 256) xd[idx] = xs[idx];
        {   // adj_avg tile: 4 rows x 32 j, one entry per lane
            int ii = lane >> 5, jj = lane & 31;
            float s = 0.0f;
            #pragma unroll
            for (int h = 0; h < 6; h++)
                s += wa[(((long)(b * 6 + h) * 256) + i0 + rh * 4 + ii) * 256 + j0 + jj];
            a_s[g][lane] = s * inv6;
        }
        __syncthreads();
        #pragma unroll
        for (int gg = 0; gg < 32; gg += 4) {
            float xv0 = x_s[(gg + 0) * 128 + lane];
            float xv1 = x_s[(gg + 1) * 128 + lane];
            float xv2 = x_s[(gg + 2) * 128 + lane];
            float xv3 = x_s[(gg + 3) * 128 + lane];
            u64 xp0 = pk2(xv0, xv1), xp1 = pk2(xv2, xv3);
            #pragma unroll
            for (int ii = 0; ii < 4; ii++) {
                const u64* ap = (const u64*)&a_s[g][ii * 32 + gg];   // broadcast LDS.64
                acc[ii] = fma2(ap[0], xp0, acc[ii]);
                acc[ii] = fma2(ap[1], xp1, acc[ii]);
            }
        }
        __syncthreads();
    }
    // partials -> pool, then reduce the two j-halves
    #pragma unroll
    for (int ii = 0; ii < 4; ii++) pool[g * 512 + ii * 128 + lane] = sum2(acc[ii]);
    __syncthreads();
    #pragma unroll
    for (int idx = tid; idx < 1024; idx += 512) {
        int r = idx >> 7, c = idx & 127;
        int rhh = r >> 2, rr = r & 3;
        t_s[idx] = pool[rhh * 512 + rr * 128 + c] + pool[(2 + rhh) * 512 + rr * 128 + c];
    }
    __syncthreads();

    // ---------- Phase B: gcn = relu(t @ Ww^T + b), 2 rows per group ----------
    float* w_s = pool;   // 32 x 129 tile, conflict-free transpose staging
    u64 b2[2];
    b2[0] = b2[1] = 0ull;
    for (int kt = 0; kt < 4; kt++) {
        int k0 = kt * 32;
        #pragma unroll
        for (int idx = tid; idx < 4096; idx += 512) {
            int d = idx >> 5, c = idx & 31;
            w_s[c * 129 + d] = Ww[d * 128 + k0 + c];   // coalesced read, cf write
        }
        __syncthreads();
        #pragma unroll
        for (int kk = 0; kk < 32; kk += 2) {
            u64 wp = pk2(w_s[kk * 129 + lane], w_s[(kk + 1) * 129 + lane]);
            #pragma unroll
            for (int r = 0; r < 2; r++) {
                u64 t2 = *(const u64*)&t_s[(g * 2 + r) * 128 + k0 + kk];  // broadcast
                b2[r] = fma2(t2, wp, b2[r]);
            }
        }
        __syncthreads();
    }
    float bb = Wb[lane];
    #pragma unroll
    for (int r = 0; r < 2; r++)
        g_s[(g * 2 + r) * 128 + lane] = fmaxf(sum2(b2[r]) + bb, 0.0f);
    __syncthreads();

    // ---------- Phase C: out = gcn @ Wxx^T + b ----------
    u64 o2[2];
    o2[0] = o2[1] = 0ull;
    for (int kt = 0; kt < 4; kt++) {
        int k0 = kt * 32;
        #pragma unroll
        for (int idx = tid; idx < 4096; idx += 512) {
            int d = idx >> 5, c = idx & 31;
            w_s[c * 129 + d] = Wxx[d * 128 + k0 + c];
        }
        __syncthreads();
        #pragma unroll
        for (int kk = 0; kk < 32; kk += 2) {
            u64 wp = pk2(w_s[kk * 129 + lane], w_s[(kk + 1) * 129 + lane]);
            #pragma unroll
            for (int r = 0; r < 2; r++) {
                u64 g2 = *(const u64*)&g_s[(g * 2 + r) * 128 + k0 + kk];
                o2[r] = fma2(g2, wp, o2[r]);
            }
        }
        __syncthreads();
    }
    float ob = Wxxb[lane];
    #pragma unroll
    for (int r = 0; r < 2; r++)
        out[(long)(r0 + g * 2 + r) * 128 + lane] = sum2(o2[r]) + ob;

    // ---------- Phase D: n1/n2 — 96 dots of length 128 ----------
    if (tid < 96) {
        int sel = tid >= 48;                // 0 -> n1, 1 -> n2
        int q   = tid - sel * 48;
        int r   = q / 6, k = q % 6;
        const float* gp = &g_s[r * 128];
        const float* w  = Wx_w + k * 294 + 6 + sel * 128;
        u64 s = 0ull;
        #pragma unroll 8
        for (int d = 0; d < 128; d += 2)
            s = fma2(*(const u64*)&gp[d], pk2(__ldg(&w[d]), __ldg(&w[d + 1])), s);
        float v = sum2(s);
        if (sel == 0) g_n1[(r0 + r) * 8 + k]   = v;
        else          g_n2T[k * 2048 + r0 + r] = v;
    }
}

// ---------------------------------------------------------------------------
// new_adj[b,k,i,j] = sum_h wa[b,h,i,j]*Wa[k,h] + n1[b,i,k] + n2[b,j,k]
//                  + sum_e e[b,i,j,e]*We[k,e] + Wx_b[k]
// grid = B*L = 2048 blocks (one per (b,i)), 256 threads (thread = j)
// PDL: heavy phase (e + adj terms) runs BEFORE the grid dependency sync,
// overlapping with k_gcn; n1/n2 are read only after the sync.
// ---------------------------------------------------------------------------
__global__ void __launch_bounds__(256, 6) k_adj(const float* __restrict__ wa,
                                                const float* __restrict__ e,
                                                const float* __restrict__ Wx_w,
                                                const float* __restrict__ Wx_b,
                                                float* __restrict__ adj_out) {
    __shared__ __align__(16) float e_s[256 * 36];  // [j][ee] pad 36: .128 reads, cf
    __shared__ __align__(16) float Wa_s[40];       // [k*6+h]
    __shared__ __align__(16) float We_s[200];      // [k*32+ee]
    __shared__ __align__(16) float n1b_s[16];      // n1 @0..5, bias @8..13
    int b   = blockIdx.x >> 8;
    int i   = blockIdx.x & 255;
    int tid = threadIdx.x;

    // async-stage e[b,i,:,:] (32KB contiguous): 8 x cp.async.cg per thread
    const float4* e4 = (const float4*)(e + (((long)b * 256 + i) * 256) * 32);
    #pragma unroll
    for (int it = 0; it < 8; it++) {
        int idx = tid + it * 256;
        unsigned dst = smem_u32(&e_s[(idx >> 3) * 36 + (idx & 7) * 4]);
        cp_async16(dst, &e4[idx]);
    }
    asm volatile("cp.async.commit_group;" ::: "memory");

    // overlap: scalar input loads while the bulk copy is in flight
    float wv[6];
    #pragma unroll
    for (int h = 0; h < 6; h++)
        wv[h] = wa[(((long)(b * 6 + h) * 256) + i) * 256 + tid];
    if (tid < 36) Wa_s[tid] = Wx_w[(tid / 6) * 294 + tid % 6];
    if (tid >= 64 && tid < 256) {
        int t = tid - 64;
        We_s[t] = Wx_w[(t >> 5) * 294 + 262 + (t & 31)];
    }
    if (tid >= 48 && tid < 54) n1b_s[8 + tid - 48] = Wx_b[tid - 48];

    asm volatile("cp.async.wait_group 0;" ::: "memory");
    __syncthreads();

    u64 acc2[6];
    #pragma unroll
    for (int k = 0; k < 6; k++) acc2[k] = 0ull;

    // adj term: 3 packed h-pairs x 6 k
    u64 wp0 = pk2(wv[0], wv[1]), wp1 = pk2(wv[2], wv[3]), wp2 = pk2(wv[4], wv[5]);
    #pragma unroll
    for (int k = 0; k < 6; k++) {
        acc2[k] = fma2(*(const u64*)&Wa_s[k * 6 + 0], wp0, acc2[k]);
        acc2[k] = fma2(*(const u64*)&Wa_s[k * 6 + 2], wp1, acc2[k]);
        acc2[k] = fma2(*(const u64*)&Wa_s[k * 6 + 4], wp2, acc2[k]);
    }

    // e term: 8 x LDS.128 (conflict-free), 16 packed ee-pairs x 6 k
    const float4* ep = (const float4*)&e_s[tid * 36];
    #pragma unroll
    for (int q = 0; q < 8; q++) {
        float4 w = ep[q];
        u64 ev0 = pk2(w.x, w.y);
        u64 ev1 = pk2(w.z, w.w);
        #pragma unroll
        for (int k = 0; k < 6; k++) {
            acc2[k] = fma2(ev0, *(const u64*)&We_s[k * 32 + q * 4 + 0], acc2[k]);
            acc2[k] = fma2(ev1, *(const u64*)&We_s[k * 32 + q * 4 + 2], acc2[k]);
        }
    }

    // ---- only now do we need k_gcn's output ----
    cudaGridDependencySynchronize();

    if (tid < 6) n1b_s[tid] = g_n1[((long)b * 256 + i) * 8 + tid];
    float n2v[6];
    #pragma unroll
    for (int k = 0; k < 6; k++) n2v[k] = g_n2T[k * 2048 + b * 256 + tid];
    __syncthreads();

    long ob = ((long)(b * 6) * 65536) + (long)i * 256 + tid;
    #pragma unroll
    for (int k = 0; k < 6; k++)
        adj_out[ob + (long)k * 65536] = sum2(acc2[k]) + n1b_s[k] + n1b_s[8 + k] + n2v[k];
}

// ---------------------------------------------------------------------------
extern "C" void kernel_launch(void* const* d_in, const int* in_sizes, int n_in,
                              void* d_out, int out_size) {
    const float* x     = (const float*)d_in[0];
    const float* wa    = (const float*)d_in[1];
    const float* e     = (const float*)d_in[2];
    const float* W_w   = (const float*)d_in[3];
    const float* W_b   = (const float*)d_in[4];
    const float* Wx_w  = (const float*)d_in[5];
    const float* Wx_b  = (const float*)d_in[6];
    const float* Wxx_w = (const float*)d_in[7];
    const float* Wxx_b = (const float*)d_in[8];

    float* out     = (float*)d_out;            // (B,L,D) = 262144 floats
    float* adj_out = out + 8 * 256 * 128;      // (B,H,L,L) = 3145728 floats

    k_gcn<<<256, 512>>>(x, wa, W_w, W_b, Wx_w, Wxx_w, Wxx_b, out);

    // k_adj with programmatic dependent launch: co-schedules immediately
    // (k_gcn triggers at entry); cudaGridDependencySynchronize() guards
    // the n1/n2 reads.
    cudaLaunchConfig_t cfg = {};
    cfg.gridDim  = dim3(2048);
    cfg.blockDim = dim3(256);
    cudaLaunchAttribute attr[1];
    attr[0].id = cudaLaunchAttributeProgrammaticStreamSerialization;
    attr[0].val.programmaticStreamSerializationAllowed = 1;
    cfg.attrs    = attr;
    cfg.numAttrs = 1;
    cudaLaunchKernelEx(&cfg, k_adj, wa, e, Wx_w, Wx_b, adj_out);
}